// round 8
// baseline (speedup 1.0000x reference)
#include <cuda_runtime.h>
#include <cuda_fp16.h>

// ---------------------------------------------------------------------------
// LaplacianPyramid, unified-table version.
//
// All four layers' floor-breakpoints lie on the uniform m/4096 uv-grid
// (layer1: odd m; layers 2-4: even m), so F = f1+f2+f3+f4 is exactly
// piecewise-bilinear on that grid. We build ONE fp16 knot-PAIR table
//   K2[n][x] = (K[n][x], K[n][x+1])   (half2, 4097 x 4096 = 67 MB)
// and gather with 2 scattered 4B loads per pixel (rows y, y+1).
// Layer1 is resampled on the fly inside the fused V-pass (x-grid values are
// just copies / 2-pt averages), eliminating the expensive pack1 kernel.
// ---------------------------------------------------------------------------

__device__ __align__(16) __half2 g_K2[4097 * 4096];  // 67.1 MB
__device__ float g_H2[1024 * 4100];                  // hpass bufs (stride 4100)
__device__ float g_H3[ 512 * 4100];
__device__ float g_H4[ 256 * 4100];

template <int S>
__device__ __forceinline__ float* hbuf() {
    if constexpr (S == 1024) return g_H2;
    else if constexpr (S == 512) return g_H3;
    else return g_H4;
}

// ---- horizontal resample of small layer S onto the 4096-knot x-grid ----
template <int S>
__global__ void __launch_bounds__(256) hpass_kernel(const float* __restrict__ src) {
    int m = blockIdx.x * blockDim.x + threadIdx.x;  // [0, 4096]
    int y = blockIdx.y;                             // [0, S)
    if (m > 4096) return;
    const float sc = (float)S / 4096.0f;
    float x = fmaf((float)m, sc, -0.5f);
    float xf = floorf(x);
    float wx = x - xf;
    int x0 = (int)xf;
    const float* r = src + (long long)y * S;
    float v0 = (x0 >= 0 && x0 < S) ? __ldg(r + x0) : 0.f;
    float v1 = (x0 + 1 >= 0 && x0 + 1 < S) ? __ldg(r + x0 + 1) : 0.f;
    hbuf<S>()[y * 4100 + m] = fmaf(wx, v1 - v0, v0);
}

// ---- small-layer vertical accumulate: K[0..8] += lerp_y(H rows) ----
template <int S>
__device__ __forceinline__ void acc_small(float* K, int n, int x8, int lane) {
    const float sc = (float)S / 4096.0f;
    float yv = fmaf((float)n, sc, -0.5f);
    float yf = floorf(yv);
    float wy = yv - yf;
    int y0 = (int)yf;
    bool va = (y0 >= 0) & (y0 < S);
    bool vb = (y0 + 1 >= 0) & (y0 + 1 < S);
    const float* H = hbuf<S>();
    const float* ra = H + y0 * 4100 + x8;
    const float* rb = ra + 4100;

    float4 a03 = make_float4(0, 0, 0, 0), a47 = a03, b03 = a03, b47 = a03;
    if (va) { a03 = *(const float4*)ra; a47 = *(const float4*)(ra + 4); }
    if (vb) { b03 = *(const float4*)rb; b47 = *(const float4*)(rb + 4); }
    float a8 = __shfl_down_sync(0xffffffffu, a03.x, 1);
    float b8 = __shfl_down_sync(0xffffffffu, b03.x, 1);
    if (lane == 31) {  // x8+8 <= 4096, in range of width-4097 rows
        a8 = va ? __ldg(ra + 8) : 0.f;
        b8 = vb ? __ldg(rb + 8) : 0.f;
    }
    float a[9] = {a03.x, a03.y, a03.z, a03.w, a47.x, a47.y, a47.z, a47.w, a8};
    float b[9] = {b03.x, b03.y, b03.z, b03.w, b47.x, b47.y, b47.z, b47.w, b8};
#pragma unroll
    for (int k = 0; k < 9; k++) K[k] += fmaf(wy, b[k] - a[k], a[k]);
}

// ---- fused V-pass + pair-pack: 8 pairs (9 knots) per thread ----
__global__ void __launch_bounds__(256) vpack_kernel(const float* __restrict__ l1) {
    int t = blockIdx.x * 256 + threadIdx.x;  // [0, 511]
    int n = blockIdx.y;                      // [0, 4096]
    int x8 = t * 8;                          // knot col base [0, 4088]
    int lane = threadIdx.x & 31;

    float K[9];
#pragma unroll
    for (int k = 0; k < 9; k++) K[k] = 0.f;

    // ---- layer1 directly from src: x-grid value at col m is
    //      odd m: src[(m-1)/2]; even m: 0.5*(src[m/2-1]+src[m/2]) ----
    {
        float yv = fmaf((float)n, 0.5f, -0.5f);
        float yf = floorf(yv);
        float wy = yv - yf;
        int y0 = (int)yf;                   // [-1, 2047]
        bool va = (y0 >= 0);
        bool vb = (y0 + 1 <= 2047);
        int j = t * 4;                      // src col base [0, 2044]
        const float* ra = l1 + (long long)y0 * 2048 + j;
        const float* rb = ra + 2048;

        float4 qa = make_float4(0, 0, 0, 0), qb = qa;
        if (va) qa = *(const float4*)ra;
        if (vb) qb = *(const float4*)rb;
        float la = __shfl_up_sync(0xffffffffu, qa.w, 1);
        float lb = __shfl_up_sync(0xffffffffu, qb.w, 1);
        float rr = __shfl_down_sync(0xffffffffu, qa.x, 1);
        float rs = __shfl_down_sync(0xffffffffu, qb.x, 1);
        if (lane == 0) {
            la = (va && j >= 1) ? __ldg(ra - 1) : 0.f;
            lb = (vb && j >= 1) ? __ldg(rb - 1) : 0.f;
        }
        if (lane == 31) {
            rr = (va && j + 4 <= 2047) ? __ldg(ra + 4) : 0.f;
            rs = (vb && j + 4 <= 2047) ? __ldg(rb + 4) : 0.f;
        }
        float ha[9], hb[9];
        ha[0] = 0.5f * (la + qa.x);   hb[0] = 0.5f * (lb + qb.x);
        ha[1] = qa.x;                 hb[1] = qb.x;
        ha[2] = 0.5f * (qa.x + qa.y); hb[2] = 0.5f * (qb.x + qb.y);
        ha[3] = qa.y;                 hb[3] = qb.y;
        ha[4] = 0.5f * (qa.y + qa.z); hb[4] = 0.5f * (qb.y + qb.z);
        ha[5] = qa.z;                 hb[5] = qb.z;
        ha[6] = 0.5f * (qa.z + qa.w); hb[6] = 0.5f * (qb.z + qb.w);
        ha[7] = qa.w;                 hb[7] = qb.w;
        ha[8] = 0.5f * (qa.w + rr);   hb[8] = 0.5f * (qb.w + rs);
#pragma unroll
        for (int k = 0; k < 9; k++) K[k] += fmaf(wy, hb[k] - ha[k], ha[k]);
    }

    acc_small<1024>(K, n, x8, lane);
    acc_small<512>(K, n, x8, lane);
    acc_small<256>(K, n, x8, lane);

    // pack 8 overlapping pairs -> half2, store as two float4
    __align__(16) __half2 p[8];
#pragma unroll
    for (int k = 0; k < 8; k++) p[k] = __floats2half2_rn(K[k], K[k + 1]);
    float4* dst = reinterpret_cast<float4*>(g_K2 + (long long)n * 4096 + x8);
    dst[0] = reinterpret_cast<float4*>(p)[0];
    dst[1] = reinterpret_cast<float4*>(p)[1];
}

// ---- gather: 2 px/thread, 2 scattered 4B loads per pixel ----
__global__ void __launch_bounds__(256) gather_kernel(
    const float4* __restrict__ uv2, float2* __restrict__ out2, int npair) {
    int i = blockIdx.x * blockDim.x + threadIdx.x;
    if (i >= npair) return;
    float4 g = __ldcs(uv2 + i);

    float xc0 = g.x * 4096.f, yc0 = g.y * 4096.f;
    float xc1 = g.z * 4096.f, yc1 = g.w * 4096.f;
    int xi0 = max(0, min((int)xc0, 4095)), yi0 = max(0, min((int)yc0, 4095));
    int xi1 = max(0, min((int)xc1, 4095)), yi1 = max(0, min((int)yc1, 4095));
    int i0 = yi0 * 4096 + xi0;
    int i1 = yi1 * 4096 + xi1;

    __half2 a0 = g_K2[i0], b0 = g_K2[i0 + 4096];
    __half2 a1 = g_K2[i1], b1 = g_K2[i1 + 4096];

    float wx0 = xc0 - (float)xi0, wy0 = yc0 - (float)yi0;
    float2 fa0 = __half22float2(a0), fb0 = __half22float2(b0);
    float top0 = fmaf(wx0, fa0.y - fa0.x, fa0.x);
    float bot0 = fmaf(wx0, fb0.y - fb0.x, fb0.x);
    float r0 = fmaf(wy0, bot0 - top0, top0);

    float wx1 = xc1 - (float)xi1, wy1 = yc1 - (float)yi1;
    float2 fa1 = __half22float2(a1), fb1 = __half22float2(b1);
    float top1 = fmaf(wx1, fa1.y - fa1.x, fa1.x);
    float bot1 = fmaf(wx1, fb1.y - fb1.x, fb1.x);
    float r1 = fmaf(wy1, bot1 - top1, top1);

    __stcs(out2 + i, make_float2(r0, r1));
}

extern "C" void kernel_launch(void* const* d_in, const int* in_sizes, int n_in,
                              void* d_out, int out_size) {
    const float* uv = (const float*)d_in[0];
    const float* l1 = (const float*)d_in[1];  // 2048 x 2048
    const float* l2 = (const float*)d_in[2];  // 1024 x 1024
    const float* l3 = (const float*)d_in[3];  // 512  x 512
    const float* l4 = (const float*)d_in[4];  // 256  x 256

    hpass_kernel<1024><<<dim3(17, 1024), 256>>>(l2);
    hpass_kernel<512><<<dim3(17, 512), 256>>>(l3);
    hpass_kernel<256><<<dim3(17, 256), 256>>>(l4);
    vpack_kernel<<<dim3(2, 4097), 256>>>(l1);

    int npair = out_size / 2;  // 8*1024*1024 / 2
    gather_kernel<<<(npair + 255) / 256, 256>>>(
        (const float4*)uv, (float2*)d_out, npair);
}

// round 9
// speedup vs baseline: 1.2231x; 1.2231x over previous
#include <cuda_runtime.h>
#include <cuda_fp16.h>

// ---------------------------------------------------------------------------
// LaplacianPyramid, unified-table + columnar build.
//
// F = f1+f2+f3+f4 is exactly piecewise-bilinear on the uniform m/4096 uv-grid
// (layer1 breakpoints at odd m, layers 2-4 at even m). One fp16 knot-pair
// table K2[n][x] = (K[n][x], K[n][x+1]) (67 MB, L2-resident); gather = 2
// scattered 4B loads per pixel (rows y, y+1).
//
// Build: each thread owns 5 knot columns and marches n, holding both active
// h-resampled rows of all 4 layers in registers. Each source element is
// loaded once; horizontal weights/taps precomputed per thread.
// ---------------------------------------------------------------------------

__device__ __align__(16) __half2 g_K2[4097 * 4096];  // 67.1 MB

// ---- generic small layer (S in {1024,512,256}): 3 source cols, taps t in {0,1}
template <int S>
struct SL {
    const float* src;
    int c0;
    float wx[5];
    int tmask;          // bit k: tap index (0/1) for knot k
    bool ok0, ok1, ok2; // col validity for c0, c0+1, c0+2
    float ha[5], hb[5];
    int prev_y0;

    __device__ __forceinline__ void setup(const float* s, int x4) {
        src = s;
        const float sc = (float)S / 4096.f;
        c0 = (int)floorf((float)x4 * sc - 0.5f);
        tmask = 0;
#pragma unroll
        for (int k = 0; k < 5; k++) {
            float xs = fmaf((float)(x4 + k), sc, -0.5f);
            float x0 = floorf(xs);
            wx[k] = xs - x0;
            if ((int)x0 != c0) tmask |= (1 << k);
        }
        ok0 = (c0 >= 0) & (c0 < S);
        ok1 = (c0 + 1 >= 0) & (c0 + 1 < S);
        ok2 = (c0 + 2 >= 0) & (c0 + 2 < S);
    }
    __device__ __forceinline__ void load_row(int row, float* h) {
        float s0 = 0.f, s1 = 0.f, s2 = 0.f;
        if (row >= 0 && row < S) {
            const float* r = src + (long long)row * S + c0;
            if (ok0) s0 = __ldg(r);
            if (ok1) s1 = __ldg(r + 1);
            if (ok2) s2 = __ldg(r + 2);
        }
#pragma unroll
        for (int k = 0; k < 5; k++) {
            bool t = (tmask >> k) & 1;
            float v0 = t ? s1 : s0;
            float v1 = t ? s2 : s1;
            h[k] = fmaf(wx[k], v1 - v0, v0);
        }
    }
    __device__ __forceinline__ void init(int n) {
        const float sc = (float)S / 4096.f;
        prev_y0 = (int)floorf(fmaf((float)n, sc, -0.5f));
        load_row(prev_y0, ha);
        load_row(prev_y0 + 1, hb);
    }
    __device__ __forceinline__ float wy_adv(int n) {
        const float sc = (float)S / 4096.f;
        float y = fmaf((float)n, sc, -0.5f);
        float y0f = floorf(y);
        int y0 = (int)y0f;
        if (y0 != prev_y0) {
#pragma unroll
            for (int k = 0; k < 5; k++) ha[k] = hb[k];
            load_row(y0 + 1, hb);
            prev_y0 = y0;
        }
        return y - y0f;
    }
};

// ---- layer1 (S=2048): fixed copy/average pattern, 4 source cols ----
struct L1S {
    const float* src;
    int j;
    bool okA, okD;  // j-1, j+2 validity (j, j+1 always valid)
    float ha[5], hb[5];
    int prev_y0;

    __device__ __forceinline__ void setup(const float* s, int x4) {
        src = s;
        j = x4 >> 1;  // x4 in [0,4092] -> j in [0,2046]
        okA = (j - 1 >= 0);
        okD = (j + 2 < 2048);
    }
    __device__ __forceinline__ void load_row(int row, float* h) {
        float s0 = 0.f, s1 = 0.f, s2 = 0.f, s3 = 0.f;
        if (row >= 0 && row < 2048) {
            const float* r = src + (long long)row * 2048 + j;
            s1 = __ldg(r);
            s2 = __ldg(r + 1);
            if (okA) s0 = __ldg(r - 1);
            if (okD) s3 = __ldg(r + 2);
        }
        h[0] = 0.5f * (s0 + s1);
        h[1] = s1;
        h[2] = 0.5f * (s1 + s2);
        h[3] = s2;
        h[4] = 0.5f * (s2 + s3);
    }
    __device__ __forceinline__ void init(int n) {
        prev_y0 = (int)floorf(fmaf((float)n, 0.5f, -0.5f));
        load_row(prev_y0, ha);
        load_row(prev_y0 + 1, hb);
    }
    __device__ __forceinline__ float wy_adv(int n) {
        float y = fmaf((float)n, 0.5f, -0.5f);
        float y0f = floorf(y);
        int y0 = (int)y0f;
        if (y0 != prev_y0) {
#pragma unroll
            for (int k = 0; k < 5; k++) ha[k] = hb[k];
            load_row(y0 + 1, hb);
            prev_y0 = y0;
        }
        return y - y0f;
    }
};

static constexpr int CH = 28;  // knot rows per block

__global__ void __launch_bounds__(128) build_kernel(
    const float* __restrict__ l1, const float* __restrict__ l2,
    const float* __restrict__ l3, const float* __restrict__ l4) {
    int tcol = blockIdx.x * 128 + threadIdx.x;  // [0, 1023]
    int x4 = tcol * 4;                          // knot col base [0, 4092]
    int n_start = blockIdx.y * CH;
    int n_end = min(n_start + CH, 4097);
    if (n_start >= 4097) return;

    L1S A;       A.setup(l1, x4);
    SL<1024> B;  B.setup(l2, x4);
    SL<512>  C;  C.setup(l3, x4);
    SL<256>  D;  D.setup(l4, x4);
    A.init(n_start); B.init(n_start); C.init(n_start); D.init(n_start);

    for (int n = n_start; n < n_end; n++) {
        float wyA = A.wy_adv(n);
        float wyB = B.wy_adv(n);
        float wyC = C.wy_adv(n);
        float wyD = D.wy_adv(n);
        float K[5];
#pragma unroll
        for (int k = 0; k < 5; k++) {
            float v = fmaf(wyA, A.hb[k] - A.ha[k], A.ha[k]);
            v += fmaf(wyB, B.hb[k] - B.ha[k], B.ha[k]);
            v += fmaf(wyC, C.hb[k] - C.ha[k], C.ha[k]);
            v += fmaf(wyD, D.hb[k] - D.ha[k], D.ha[k]);
            K[k] = v;
        }
        __align__(16) __half2 p[4];
#pragma unroll
        for (int k = 0; k < 4; k++) p[k] = __floats2half2_rn(K[k], K[k + 1]);
        *reinterpret_cast<float4*>(g_K2 + (long long)n * 4096 + x4) =
            *reinterpret_cast<float4*>(p);
    }
}

// ---- gather: 2 px/thread, 2 scattered 4B loads per pixel (rows y, y+1) ----
__global__ void __launch_bounds__(256) gather_kernel(
    const float4* __restrict__ uv2, float2* __restrict__ out2, int npair) {
    int i = blockIdx.x * blockDim.x + threadIdx.x;
    if (i >= npair) return;
    float4 g = __ldcs(uv2 + i);

    float xc0 = g.x * 4096.f, yc0 = g.y * 4096.f;
    float xc1 = g.z * 4096.f, yc1 = g.w * 4096.f;
    int xi0 = max(0, min((int)xc0, 4095)), yi0 = max(0, min((int)yc0, 4095));
    int xi1 = max(0, min((int)xc1, 4095)), yi1 = max(0, min((int)yc1, 4095));
    int i0 = yi0 * 4096 + xi0;
    int i1 = yi1 * 4096 + xi1;

    __half2 a0 = g_K2[i0], b0 = g_K2[i0 + 4096];
    __half2 a1 = g_K2[i1], b1 = g_K2[i1 + 4096];

    float wx0 = xc0 - (float)xi0, wy0 = yc0 - (float)yi0;
    float2 fa0 = __half22float2(a0), fb0 = __half22float2(b0);
    float top0 = fmaf(wx0, fa0.y - fa0.x, fa0.x);
    float bot0 = fmaf(wx0, fb0.y - fb0.x, fb0.x);
    float r0 = fmaf(wy0, bot0 - top0, top0);

    float wx1 = xc1 - (float)xi1, wy1 = yc1 - (float)yi1;
    float2 fa1 = __half22float2(a1), fb1 = __half22float2(b1);
    float top1 = fmaf(wx1, fa1.y - fa1.x, fa1.x);
    float bot1 = fmaf(wx1, fb1.y - fb1.x, fb1.x);
    float r1 = fmaf(wy1, bot1 - top1, top1);

    __stcs(out2 + i, make_float2(r0, r1));
}

extern "C" void kernel_launch(void* const* d_in, const int* in_sizes, int n_in,
                              void* d_out, int out_size) {
    const float* uv = (const float*)d_in[0];
    const float* l1 = (const float*)d_in[1];  // 2048 x 2048
    const float* l2 = (const float*)d_in[2];  // 1024 x 1024
    const float* l3 = (const float*)d_in[3];  // 512  x 512
    const float* l4 = (const float*)d_in[4];  // 256  x 256

    build_kernel<<<dim3(8, (4097 + CH - 1) / CH), 128>>>(l1, l2, l3, l4);

    int npair = out_size / 2;  // 8*1024*1024 / 2
    gather_kernel<<<(npair + 255) / 256, 256>>>(
        (const float4*)uv, (float2*)d_out, npair);
}

// round 13
// speedup vs baseline: 1.2429x; 1.0162x over previous
#include <cuda_runtime.h>
#include <cuda_fp16.h>
#include <cstdint>

// ---------------------------------------------------------------------------
// LaplacianPyramid, unified-table + columnar build + L2 eviction policy.
//
// F = f1+f2+f3+f4 is exactly piecewise-bilinear on the uniform m/4096 uv-grid.
// One fp16 knot-pair table K2[n][x] = (K[n][x], K[n][x+1]) (67 MB), accessed
// with a createpolicy L2::evict_last cache-hint so it stays L2-resident while
// uv/out stream through with .cs (evict-first).
// ---------------------------------------------------------------------------

__device__ __align__(16) __half2 g_K2[4097 * 4096];  // 67.1 MB

// ---- L2 evict-last policy helpers (createpolicy + cache_hint forms) ----
__device__ __forceinline__ uint64_t mk_evl_policy() {
    uint64_t p;
    asm("createpolicy.fractional.L2::evict_last.b64 %0, 1.0;" : "=l"(p));
    return p;
}
__device__ __forceinline__ float2 ld_pair_evl(const __half2* p, uint64_t pol) {
    uint32_t v;
    asm volatile("ld.global.nc.L2::cache_hint.b32 %0, [%1], %2;"
                 : "=r"(v) : "l"(p), "l"(pol));
    __half2 h = *reinterpret_cast<__half2*>(&v);
    return __half22float2(h);
}
__device__ __forceinline__ void st_f4_evl(void* p, float4 v, uint64_t pol) {
    asm volatile("st.global.L2::cache_hint.v4.f32 [%0], {%1,%2,%3,%4}, %5;"
                 :: "l"(p), "f"(v.x), "f"(v.y), "f"(v.z), "f"(v.w), "l"(pol)
                 : "memory");
}

// ---- generic small layer (S in {1024,512,256}): 3 source cols ----
template <int S>
struct SL {
    const float* src;
    int c0;
    float wx[5];
    int tmask;
    bool ok0, ok1, ok2;
    float ha[5], hb[5];
    int prev_y0;

    __device__ __forceinline__ void setup(const float* s, int x4) {
        src = s;
        const float sc = (float)S / 4096.f;
        c0 = (int)floorf((float)x4 * sc - 0.5f);
        tmask = 0;
#pragma unroll
        for (int k = 0; k < 5; k++) {
            float xs = fmaf((float)(x4 + k), sc, -0.5f);
            float x0 = floorf(xs);
            wx[k] = xs - x0;
            if ((int)x0 != c0) tmask |= (1 << k);
        }
        ok0 = (c0 >= 0) & (c0 < S);
        ok1 = (c0 + 1 >= 0) & (c0 + 1 < S);
        ok2 = (c0 + 2 >= 0) & (c0 + 2 < S);
    }
    __device__ __forceinline__ void load_row(int row, float* h) {
        float s0 = 0.f, s1 = 0.f, s2 = 0.f;
        if (row >= 0 && row < S) {
            const float* r = src + (long long)row * S + c0;
            if (ok0) s0 = __ldcs(r);
            if (ok1) s1 = __ldcs(r + 1);
            if (ok2) s2 = __ldcs(r + 2);
        }
#pragma unroll
        for (int k = 0; k < 5; k++) {
            bool t = (tmask >> k) & 1;
            float v0 = t ? s1 : s0;
            float v1 = t ? s2 : s1;
            h[k] = fmaf(wx[k], v1 - v0, v0);
        }
    }
    __device__ __forceinline__ void init(int n) {
        const float sc = (float)S / 4096.f;
        prev_y0 = (int)floorf(fmaf((float)n, sc, -0.5f));
        load_row(prev_y0, ha);
        load_row(prev_y0 + 1, hb);
    }
    __device__ __forceinline__ float wy_adv(int n) {
        const float sc = (float)S / 4096.f;
        float y = fmaf((float)n, sc, -0.5f);
        float y0f = floorf(y);
        int y0 = (int)y0f;
        if (y0 != prev_y0) {
#pragma unroll
            for (int k = 0; k < 5; k++) ha[k] = hb[k];
            load_row(y0 + 1, hb);
            prev_y0 = y0;
        }
        return y - y0f;
    }
};

// ---- layer1 (S=2048): fixed copy/average pattern ----
struct L1S {
    const float* src;
    int j;
    bool okA, okD;
    float ha[5], hb[5];
    int prev_y0;

    __device__ __forceinline__ void setup(const float* s, int x4) {
        src = s;
        j = x4 >> 1;
        okA = (j - 1 >= 0);
        okD = (j + 2 < 2048);
    }
    __device__ __forceinline__ void load_row(int row, float* h) {
        float s0 = 0.f, s1 = 0.f, s2 = 0.f, s3 = 0.f;
        if (row >= 0 && row < 2048) {
            const float* r = src + (long long)row * 2048 + j;
            s1 = __ldcs(r);
            s2 = __ldcs(r + 1);
            if (okA) s0 = __ldcs(r - 1);
            if (okD) s3 = __ldcs(r + 2);
        }
        h[0] = 0.5f * (s0 + s1);
        h[1] = s1;
        h[2] = 0.5f * (s1 + s2);
        h[3] = s2;
        h[4] = 0.5f * (s2 + s3);
    }
    __device__ __forceinline__ void init(int n) {
        prev_y0 = (int)floorf(fmaf((float)n, 0.5f, -0.5f));
        load_row(prev_y0, ha);
        load_row(prev_y0 + 1, hb);
    }
    __device__ __forceinline__ float wy_adv(int n) {
        float y = fmaf((float)n, 0.5f, -0.5f);
        float y0f = floorf(y);
        int y0 = (int)y0f;
        if (y0 != prev_y0) {
#pragma unroll
            for (int k = 0; k < 5; k++) ha[k] = hb[k];
            load_row(y0 + 1, hb);
            prev_y0 = y0;
        }
        return y - y0f;
    }
};

static constexpr int CH = 12;  // knot rows per block

__global__ void __launch_bounds__(128) build_kernel(
    const float* __restrict__ l1, const float* __restrict__ l2,
    const float* __restrict__ l3, const float* __restrict__ l4) {
    int tcol = blockIdx.x * 128 + threadIdx.x;  // [0, 1023]
    int x4 = tcol * 4;                          // knot col base [0, 4092]
    int n_start = blockIdx.y * CH;
    int n_end = min(n_start + CH, 4097);
    if (n_start >= 4097) return;

    uint64_t pol = mk_evl_policy();

    L1S A;       A.setup(l1, x4);
    SL<1024> B;  B.setup(l2, x4);
    SL<512>  C;  C.setup(l3, x4);
    SL<256>  D;  D.setup(l4, x4);
    A.init(n_start); B.init(n_start); C.init(n_start); D.init(n_start);

    for (int n = n_start; n < n_end; n++) {
        float wyA = A.wy_adv(n);
        float wyB = B.wy_adv(n);
        float wyC = C.wy_adv(n);
        float wyD = D.wy_adv(n);
        float K[5];
#pragma unroll
        for (int k = 0; k < 5; k++) {
            float v = fmaf(wyA, A.hb[k] - A.ha[k], A.ha[k]);
            v += fmaf(wyB, B.hb[k] - B.ha[k], B.ha[k]);
            v += fmaf(wyC, C.hb[k] - C.ha[k], C.ha[k]);
            v += fmaf(wyD, D.hb[k] - D.ha[k], D.ha[k]);
            K[k] = v;
        }
        __align__(16) __half2 p[4];
#pragma unroll
        for (int k = 0; k < 4; k++) p[k] = __floats2half2_rn(K[k], K[k + 1]);
        st_f4_evl(g_K2 + (long long)n * 4096 + x4,
                  *reinterpret_cast<float4*>(p), pol);
    }
}

// ---- gather: 2 px/thread, 2 scattered evict_last 4B loads per pixel ----
__global__ void __launch_bounds__(256) gather_kernel(
    const float4* __restrict__ uv2, float2* __restrict__ out2, int npair) {
    int i = blockIdx.x * blockDim.x + threadIdx.x;
    if (i >= npair) return;
    uint64_t pol = mk_evl_policy();
    float4 g = __ldcs(uv2 + i);

    float xc0 = g.x * 4096.f, yc0 = g.y * 4096.f;
    float xc1 = g.z * 4096.f, yc1 = g.w * 4096.f;
    int xi0 = max(0, min((int)xc0, 4095)), yi0 = max(0, min((int)yc0, 4095));
    int xi1 = max(0, min((int)xc1, 4095)), yi1 = max(0, min((int)yc1, 4095));
    int i0 = yi0 * 4096 + xi0;
    int i1 = yi1 * 4096 + xi1;

    float2 fa0 = ld_pair_evl(g_K2 + i0, pol);
    float2 fb0 = ld_pair_evl(g_K2 + i0 + 4096, pol);
    float2 fa1 = ld_pair_evl(g_K2 + i1, pol);
    float2 fb1 = ld_pair_evl(g_K2 + i1 + 4096, pol);

    float wx0 = xc0 - (float)xi0, wy0 = yc0 - (float)yi0;
    float top0 = fmaf(wx0, fa0.y - fa0.x, fa0.x);
    float bot0 = fmaf(wx0, fb0.y - fb0.x, fb0.x);
    float r0 = fmaf(wy0, bot0 - top0, top0);

    float wx1 = xc1 - (float)xi1, wy1 = yc1 - (float)yi1;
    float top1 = fmaf(wx1, fa1.y - fa1.x, fa1.x);
    float bot1 = fmaf(wx1, fb1.y - fb1.x, fb1.x);
    float r1 = fmaf(wy1, bot1 - top1, top1);

    __stcs(out2 + i, make_float2(r0, r1));
}

extern "C" void kernel_launch(void* const* d_in, const int* in_sizes, int n_in,
                              void* d_out, int out_size) {
    const float* uv = (const float*)d_in[0];
    const float* l1 = (const float*)d_in[1];  // 2048 x 2048
    const float* l2 = (const float*)d_in[2];  // 1024 x 1024
    const float* l3 = (const float*)d_in[3];  // 512  x 512
    const float* l4 = (const float*)d_in[4];  // 256  x 256

    build_kernel<<<dim3(8, (4097 + CH - 1) / CH), 128>>>(l1, l2, l3, l4);

    int npair = out_size / 2;  // 8*1024*1024 / 2
    gather_kernel<<<(npair + 255) / 256, 256>>>(
        (const float4*)uv, (float2*)d_out, npair);
}